// round 4
// baseline (speedup 1.0000x reference)
#include <cuda_runtime.h>
#include <math.h>

using ull = unsigned long long;

constexpr int T_STEPS = 28;
constexpr int B_TOT   = 16384;
constexpr int X_DIM   = 28;
constexpr int H_DIM   = 100;
constexpr int Z_DIM   = 16;
constexpr int TB      = 64;              // batch rows per block (2 per lane)
constexpr int NBLK    = B_TOT / TB;      // 256
constexpr int NTHR    = 256;             // 8 warps

// row strides (floats). All satisfy (stride*i mod 32) distinct for i=0..7
// -> conflict-free LDS.128 across a warp.
constexpr int SX = 28;    // x / probs buffers
constexpr int SZ = 20;    // z-sized buffers (16 padded to 20)
constexpr int SH = 100;   // h-sized buffers

__device__ float        g_part[NBLK * 2];
__device__ unsigned int g_done;

enum { ACT_LIN = 0, ACT_RELU = 1, ACT_SIG = 2, ACT_SP = 3 };

__device__ __forceinline__ float act_apply(float v, int A) {
    if (A == ACT_RELU) return fmaxf(v, 0.f);
    if (A == ACT_SIG)  return 1.f / (1.f + expf(-v));
    if (A == ACT_SP)   return fmaxf(v, 0.f) + log1pf(expf(-fabsf(v)));
    return v;
}
__device__ __forceinline__ float sigf(float v) { return 1.f / (1.f + expf(-v)); }

__device__ __forceinline__ ull fma2(ull a, ull b, ull c) {
    ull d; asm("fma.rn.f32x2 %0,%1,%2,%3;" : "=l"(d) : "l"(a), "l"(b), "l"(c));
    return d;
}
// horizontal sum of the two packed f32 lanes (even-k + odd-k partials)
__device__ __forceinline__ float hsum(ull v) {
    float2 f; asm("mov.b64 {%0,%1},%2;" : "=f"(f.x), "=f"(f.y) : "l"(v));
    return f.x + f.y;
}

// ---------------------------------------------------------------------------
// GEMM pass: NO outputs, activations row-major act[row*S + k].
// Lane handles rows (lane, lane+32). K packed in f32x2; weights LDG.128.
// out[row*SO + o] = act( dot(W[o], a_row) + bias[o] )
template <int NO, int K4A, int SA, int K4B, int SB, int SO, int ACT>
__device__ __forceinline__ void gpass(
    const float* __restrict__ W, const float* __restrict__ bias,
    const float* __restrict__ aA, const float* __restrict__ aB,
    float* __restrict__ out, int o0, int lane)
{
    constexpr int K = 4 * (K4A + K4B);
    ull acc0[NO], acc1[NO];
#pragma unroll
    for (int i = 0; i < NO; i++) { acc0[i] = 0ull; acc1[i] = 0ull; }

    {
        const float* a0p = aA + lane * SA;
        const float* a1p = aA + (lane + 32) * SA;
#pragma unroll 2
        for (int k4 = 0; k4 < K4A; k4++) {
            ulonglong2 a0 = *reinterpret_cast<const ulonglong2*>(a0p + 4 * k4);
            ulonglong2 a1 = *reinterpret_cast<const ulonglong2*>(a1p + 4 * k4);
#pragma unroll
            for (int i = 0; i < NO; i++) {
                ulonglong2 w = *reinterpret_cast<const ulonglong2*>(
                    W + (size_t)(o0 + i) * K + 4 * k4);
                acc0[i] = fma2(w.x, a0.x, acc0[i]);
                acc0[i] = fma2(w.y, a0.y, acc0[i]);
                acc1[i] = fma2(w.x, a1.x, acc1[i]);
                acc1[i] = fma2(w.y, a1.y, acc1[i]);
            }
        }
    }
    if constexpr (K4B > 0) {
        const float* b0p = aB + lane * SB;
        const float* b1p = aB + (lane + 32) * SB;
#pragma unroll 2
        for (int k4 = 0; k4 < K4B; k4++) {
            ulonglong2 a0 = *reinterpret_cast<const ulonglong2*>(b0p + 4 * k4);
            ulonglong2 a1 = *reinterpret_cast<const ulonglong2*>(b1p + 4 * k4);
#pragma unroll
            for (int i = 0; i < NO; i++) {
                ulonglong2 w = *reinterpret_cast<const ulonglong2*>(
                    W + (size_t)(o0 + i) * K + 4 * K4A + 4 * k4);
                acc0[i] = fma2(w.x, a0.x, acc0[i]);
                acc0[i] = fma2(w.y, a0.y, acc0[i]);
                acc1[i] = fma2(w.x, a1.x, acc1[i]);
                acc1[i] = fma2(w.y, a1.y, acc1[i]);
            }
        }
    }
#pragma unroll
    for (int i = 0; i < NO; i++) {
        float b = bias[o0 + i];
        out[lane * SO + o0 + i]        = act_apply(hsum(acc0[i]) + b, ACT);
        out[(lane + 32) * SO + o0 + i] = act_apply(hsum(acc1[i]) + b, ACT);
    }
}

// Nout=100, single pass per warp: warps 0-3 -> 12 outs, warps 4-7 -> 13.
template <int K4A, int SA, int K4B, int SB, int SO, int ACT>
__device__ __forceinline__ void gemm100(
    const float* __restrict__ W, const float* __restrict__ bias,
    const float* __restrict__ aA, const float* __restrict__ aB,
    float* __restrict__ out, int warp, int lane)
{
    if (warp < 4)
        gpass<12, K4A, SA, K4B, SB, SO, ACT>(W, bias, aA, aB, out, warp * 12, lane);
    else
        gpass<13, K4A, SA, K4B, SB, SO, ACT>(W, bias, aA, aB, out, 48 + (warp - 4) * 13, lane);
}

// ---------------------------------------------------------------------------
// GRU segment: accumulate gate rows (j0, j0+1) for r,u (slots 0..3) and the
// n-gate into slots NS,NS+1 (NS=4 for Wih's n_i, NS=6 for Whh's n_h).
// A0/A1 = rowset accumulators (rows lane / lane+32).
template <int NS>
__device__ __forceinline__ void gru_seg(
    ull* __restrict__ A0, ull* __restrict__ A1,
    const float* __restrict__ W, int ldw, int j0, int col0,
    const float* __restrict__ act, int lane)
{
    const float* a0p = act + lane * SH;
    const float* a1p = act + (lane + 32) * SH;
    const float* wr  = W + (size_t)j0 * ldw + col0;
    const size_t g1  = (size_t)100 * ldw;   // gate stride in W
#pragma unroll 1
    for (int k4 = 0; k4 < 25; k4++) {
        ulonglong2 a0 = *reinterpret_cast<const ulonglong2*>(a0p + 4 * k4);
        ulonglong2 a1 = *reinterpret_cast<const ulonglong2*>(a1p + 4 * k4);
#pragma unroll
        for (int g = 0; g < 6; g++) {
            const int gate = g >> 1, jj = g & 1;
            const int slot = (gate < 2) ? (2 * gate + jj) : (NS + jj);
            ulonglong2 w = *reinterpret_cast<const ulonglong2*>(
                wr + (size_t)gate * g1 + (size_t)jj * ldw + 4 * k4);
            A0[slot] = fma2(w.x, a0.x, A0[slot]);
            A0[slot] = fma2(w.y, a0.y, A0[slot]);
            A1[slot] = fma2(w.x, a1.x, A1[slot]);
            A1[slot] = fma2(w.y, a1.y, A1[slot]);
        }
    }
}

// ---------------------------------------------------------------------------
__global__ void __launch_bounds__(NTHR, 1) vrnn_main(
    const float* __restrict__ x,      const float* __restrict__ eps,
    const float* __restrict__ Wpx,    const float* __restrict__ bpx,
    const float* __restrict__ Wpz,    const float* __restrict__ bpz,
    const float* __restrict__ Wp1,    const float* __restrict__ bp1,
    const float* __restrict__ Wp_mu,  const float* __restrict__ bp_mu,
    const float* __restrict__ Wp_sig, const float* __restrict__ bp_sig,
    const float* __restrict__ We1,    const float* __restrict__ be1,
    const float* __restrict__ We_mu,  const float* __restrict__ be_mu,
    const float* __restrict__ We_sig, const float* __restrict__ be_sig,
    const float* __restrict__ Wd1,    const float* __restrict__ bd1,
    const float* __restrict__ Wd2,    const float* __restrict__ bd2,
    const float* __restrict__ Wd3,    const float* __restrict__ bd3,
    const float* __restrict__ Wih,    const float* __restrict__ Whh,
    const float* __restrict__ bih,    const float* __restrict__ bhh,
    float* __restrict__ out)
{
    extern __shared__ float s[];
    // row-major buffers
    float* xs   = s;                      // 64*28
    float* es   = xs   + TB * SX;         // 64*20
    float* zb   = es   + TB * SZ;         // 64*20
    float* emu  = zb   + TB * SZ;         // 64*20
    float* esg  = emu  + TB * SZ;
    float* pmu  = esg  + TB * SZ;
    float* psg  = pmu  + TB * SZ;
    float* prb  = psg  + TB * SZ;         // 64*28
    float* h0   = prb  + TB * SX;         // 64*100
    float* h1   = h0   + TB * SH;
    float* px   = h1   + TB * SH;
    float* pz   = px   + TB * SH;
    float* bufA = pz   + TB * SH;
    float* bufB = bufA + TB * SH;

    __shared__ int s_last;

    const int tid  = threadIdx.x;
    const int lane = tid & 31;
    const int warp = tid >> 5;
    const int b0   = blockIdx.x * TB;

    for (int i = tid; i < SH * TB; i += NTHR) h0[i] = 0.f;

    float kl_acc = 0.f, nll_acc = 0.f;
    float* hc = h0;
    float* hn = h1;

    for (int t = 0; t < T_STEPS; t++) {
        // ---- stage inputs (x is already row-major [row][28] -> direct copy)
        const float* xg = x   + ((size_t)t * B_TOT + b0) * X_DIM;
        const float* eg = eps + ((size_t)t * B_TOT + b0) * Z_DIM;
        for (int i = tid; i < X_DIM * TB; i += NTHR) xs[i] = xg[i];
        for (int i = tid; i < Z_DIM * TB; i += NTHR) {
            int r = i >> 4, k = i & 15;
            es[r * SZ + k] = eg[i];
        }
        __syncthreads();

        // 1. px = relu(Wpx x + b)              [100, K=28]
        gemm100<7, SX, 0, SX, SH, ACT_RELU>(Wpx, bpx, xs, nullptr, px, warp, lane);
        __syncthreads();

        // 2. he = relu(We1 [px;h]) -> bufA     [100, K=200]
        gemm100<25, SH, 25, SH, SH, ACT_RELU>(We1, be1, px, hc, bufA, warp, lane);
        // 3. hp = relu(Wp1 h) -> bufB          [100, K=100]
        gemm100<25, SH, 0, SH, SH, ACT_RELU>(Wp1, bp1, hc, nullptr, bufB, warp, lane);
        __syncthreads();

        // 4. heads (16 outs each, K=100): 2 warps per matrix, NO=8
        if (warp < 2)
            gpass<8, 25, SH, 0, SH, SZ, ACT_LIN>(We_mu,  be_mu,  bufA, nullptr, emu, (warp & 1) * 8, lane);
        else if (warp < 4)
            gpass<8, 25, SH, 0, SH, SZ, ACT_SP >(We_sig, be_sig, bufA, nullptr, esg, (warp & 1) * 8, lane);
        else if (warp < 6)
            gpass<8, 25, SH, 0, SH, SZ, ACT_LIN>(Wp_mu,  bp_mu,  bufB, nullptr, pmu, (warp & 1) * 8, lane);
        else
            gpass<8, 25, SH, 0, SH, SZ, ACT_SP >(Wp_sig, bp_sig, bufB, nullptr, psg, (warp & 1) * 8, lane);
        __syncthreads();

        // 5. z = enc_mu + sqrt(enc_sig)*eps
        for (int i = tid; i < Z_DIM * TB; i += NTHR) {
            int r = i >> 4, k = i & 15;
            int idx = r * SZ + k;
            zb[idx] = emu[idx] + sqrtf(esg[idx]) * es[idx];
        }
        __syncthreads();

        // 6. pz = relu(Wpz z + b)              [100, K=16]
        gemm100<4, SZ, 0, SZ, SH, ACT_RELU>(Wpz, bpz, zb, nullptr, pz, warp, lane);
        __syncthreads();

        // 7. hd1 = relu(Wd1 [pz;h]) -> bufA    [100, K=200]
        gemm100<25, SH, 25, SH, SH, ACT_RELU>(Wd1, bd1, pz, hc, bufA, warp, lane);
        __syncthreads();

        // 8. hd2 = relu(Wd2 hd1) -> bufB       [100, K=100]
        gemm100<25, SH, 0, SH, SH, ACT_RELU>(Wd2, bd2, bufA, nullptr, bufB, warp, lane);
        __syncthreads();

        // 9. probs = sigmoid(Wd3 hd2 + b)  [28, K=100]
        //    Load-balance: warps 0,1 get 7 GRU tasks below, so Wd3's 7 chunks
        //    go to warps 2-7 (warp 2 takes two).
        if (warp >= 2) {
            gpass<4, 25, SH, 0, SH, SX, ACT_SIG>(Wd3, bd3, bufB, nullptr, prb, (warp - 2) * 4, lane);
            if (warp == 2)
                gpass<4, 25, SH, 0, SH, SX, ACT_SIG>(Wd3, bd3, bufB, nullptr, prb, 24, lane);
        }

        // 10. GRU: tasks of 2 j's; 50 tasks over 8 warps
        for (int task = warp; task < 50; task += 8) {
            const int j0 = 2 * task;
            ull A0[8], A1[8];   // [r0,r1,u0,u1,ni0,ni1,nh0,nh1]
#pragma unroll
            for (int i = 0; i < 8; i++) { A0[i] = 0ull; A1[i] = 0ull; }
            gru_seg<4>(A0, A1, Wih, 200, j0, 0,   pz, lane);
            gru_seg<4>(A0, A1, Wih, 200, j0, 100, px, lane);
            gru_seg<6>(A0, A1, Whh, 100, j0, 0,   hc, lane);
#pragma unroll
            for (int jj = 0; jj < 2; jj++) {
                const int j = j0 + jj;
                const float br = bih[j] + bhh[j];
                const float bu = bih[100 + j] + bhh[100 + j];
                const float bn = bih[200 + j];
                const float bm = bhh[200 + j];
#pragma unroll
                for (int d = 0; d < 2; d++) {
                    const ull* A = d ? A1 : A0;
                    const int r = lane + d * 32;
                    float rr = sigf(hsum(A[0 + jj]) + br);
                    float uu = sigf(hsum(A[2 + jj]) + bu);
                    float nn = tanhf(hsum(A[4 + jj]) + bn + rr * (hsum(A[6 + jj]) + bm));
                    hn[r * SH + j] = (1.f - uu) * nn + uu * hc[r * SH + j];
                }
            }
        }
        __syncthreads();

        // 11. KL + NLL: 4 threads per row split the features
        {
            const int row = tid & 63, part = tid >> 6;   // part 0..3
            const float* E = emu + row * SZ;
            const float* S = esg + row * SZ;
            const float* P = pmu + row * SZ;
            const float* Q = psg + row * SZ;
#pragma unroll
            for (int zi = 0; zi < 4; zi++) {
                int zk = part * 4 + zi;
                float ps = Q[zk] + 1e-10f;
                float dd = E[zk] - P[zk];
                float ev = S[zk];
                kl_acc += 0.5f * (2.f * logf(ps) - 2.f * logf(ev)
                                  + (ev * ev + dd * dd) / (ps * ps) - 1.f);
            }
            const float* PR = prb + row * SX;
            const float* XR = xs  + row * SX;
#pragma unroll
            for (int xi = 0; xi < 7; xi++) {
                int xk = part * 7 + xi;
                float p  = PR[xk];
                float xv = XR[xk];
                nll_acc -= xv * logf(p + 1e-10f) + (1.f - xv) * logf(1.f - p + 1e-10f);
            }
        }

        { float* tmp = hc; hc = hn; hn = tmp; }
        __syncthreads();   // protects xs/es/head bufs before next staging
    }

    // ---- block partial reduction
#pragma unroll
    for (int off = 16; off > 0; off >>= 1) {
        kl_acc  += __shfl_down_sync(0xffffffffu, kl_acc,  off);
        nll_acc += __shfl_down_sync(0xffffffffu, nll_acc, off);
    }
    if (lane == 0) { s[warp] = kl_acc; s[8 + warp] = nll_acc; }
    __syncthreads();
    if (tid == 0) {
        float k = 0.f, n = 0.f;
        for (int w = 0; w < 8; w++) { k += s[w]; n += s[8 + w]; }
        g_part[2 * blockIdx.x + 0] = k;
        g_part[2 * blockIdx.x + 1] = n;
        __threadfence();
        unsigned v = atomicAdd(&g_done, 1u);
        s_last = (v == (unsigned)(gridDim.x - 1)) ? 1 : 0;
    }
    __syncthreads();

    // ---- deterministic final reduction in the last-arriving block
    if (s_last) {
        float k = g_part[2 * tid + 0];   // NBLK == NTHR == 256
        float n = g_part[2 * tid + 1];
        s[tid] = k; s[256 + tid] = n;
        __syncthreads();
        for (int st = 128; st > 0; st >>= 1) {
            if (tid < st) { s[tid] += s[tid + st]; s[256 + tid] += s[256 + tid + st]; }
            __syncthreads();
        }
        if (tid == 0) {
            const float invB = 1.f / (float)B_TOT;
            out[0] = s[0] * invB;
            out[1] = s[256] * invB;
            g_done = 0;                  // reset for next graph replay
        }
    }
}

// ---------------------------------------------------------------------------
extern "C" void kernel_launch(void* const* d_in, const int* in_sizes, int n_in,
                              void* d_out, int out_size)
{
    (void)in_sizes; (void)n_in; (void)out_size;
    const float* x      = (const float*)d_in[0];
    const float* eps    = (const float*)d_in[1];
    const float* Wpx    = (const float*)d_in[2];
    const float* bpx    = (const float*)d_in[3];
    const float* Wpz    = (const float*)d_in[4];
    const float* bpz    = (const float*)d_in[5];
    const float* Wp1    = (const float*)d_in[6];
    const float* bp1    = (const float*)d_in[7];
    const float* Wp_mu  = (const float*)d_in[8];
    const float* bp_mu  = (const float*)d_in[9];
    const float* Wp_sig = (const float*)d_in[10];
    const float* bp_sig = (const float*)d_in[11];
    const float* We1    = (const float*)d_in[12];
    const float* be1    = (const float*)d_in[13];
    const float* We_mu  = (const float*)d_in[14];
    const float* be_mu  = (const float*)d_in[15];
    const float* We_sig = (const float*)d_in[16];
    const float* be_sig = (const float*)d_in[17];
    const float* Wd1    = (const float*)d_in[18];
    const float* bd1    = (const float*)d_in[19];
    const float* Wd2    = (const float*)d_in[20];
    const float* bd2    = (const float*)d_in[21];
    const float* Wd3    = (const float*)d_in[22];
    const float* bd3    = (const float*)d_in[23];
    const float* Wih    = (const float*)d_in[24];
    const float* Whh    = (const float*)d_in[25];
    const float* bih    = (const float*)d_in[26];
    const float* bhh    = (const float*)d_in[27];
    float* out = (float*)d_out;

    const int smem_floats =
        TB * (2 * SX + 6 * SZ + 6 * SH);            // 64*(56+120+600)=49,664
    const int smem_bytes = smem_floats * (int)sizeof(float);   // 198,656 B

    cudaFuncSetAttribute(vrnn_main,
                         cudaFuncAttributeMaxDynamicSharedMemorySize, smem_bytes);

    vrnn_main<<<NBLK, NTHR, smem_bytes>>>(
        x, eps, Wpx, bpx, Wpz, bpz, Wp1, bp1, Wp_mu, bp_mu, Wp_sig, bp_sig,
        We1, be1, We_mu, be_mu, We_sig, be_sig, Wd1, bd1, Wd2, bd2, Wd3, bd3,
        Wih, Whh, bih, bhh, out);
}

// round 5
// speedup vs baseline: 1.2185x; 1.2185x over previous
#include <cuda_runtime.h>
#include <math.h>

using ull = unsigned long long;

constexpr int T_STEPS = 28;
constexpr int B_TOT   = 16384;
constexpr int X_DIM   = 28;
constexpr int H_DIM   = 100;
constexpr int Z_DIM   = 16;
constexpr int TB      = 64;              // batch rows per block (2 per lane)
constexpr int NBLK    = B_TOT / TB;      // 256
constexpr int NTHR    = 512;             // 16 warps

__device__ float        g_part[NBLK * 2];
__device__ unsigned int g_done;

enum { ACT_LIN = 0, ACT_RELU = 1, ACT_SIG = 2, ACT_SP = 3 };

__device__ __forceinline__ float act_apply(float v, int A) {
    if (A == ACT_RELU) return fmaxf(v, 0.f);
    if (A == ACT_SIG)  return 1.f / (1.f + expf(-v));
    if (A == ACT_SP)   return fmaxf(v, 0.f) + log1pf(expf(-fabsf(v)));
    return v;
}
__device__ __forceinline__ float sigf(float v) { return 1.f / (1.f + expf(-v)); }

// ---- packed f32x2 helpers (rows lane / lane+32 packed in one 64-bit reg) --
__device__ __forceinline__ ull b2(float v) {
    ull r; asm("mov.b64 %0,{%1,%1};" : "=l"(r) : "f"(v)); return r;
}
__device__ __forceinline__ ull fma2(ull a, ull b, ull c) {
    ull d; asm("fma.rn.f32x2 %0,%1,%2,%3;" : "=l"(d) : "l"(a), "l"(b), "l"(c));
    return d;
}
__device__ __forceinline__ float2 unpk(ull v) {
    float2 f; asm("mov.b64 {%0,%1},%2;" : "=f"(f.x), "=f"(f.y) : "l"(v)); return f;
}
__device__ __forceinline__ ull pk(float x, float y) {
    ull r; asm("mov.b64 %0,{%1,%2};" : "=l"(r) : "f"(x), "f"(y)); return r;
}

// ---------------------------------------------------------------------------
// GEMM chunk: NO outputs, activations feat-major packed:
// act_u64[k*32 + lane] = rows (lane, lane+32) of feature k. Conflict-free LDS.
template <int NO>
__device__ __forceinline__ void gemm_chunk(
    const float* __restrict__ W, int K, const float* __restrict__ bias,
    const float* __restrict__ actA, int K4A,
    const float* __restrict__ actB, int K4B,
    float* __restrict__ out, int o0, int act, int lane)
{
    ull acc[NO];
    const float* wr[NO];
#pragma unroll
    for (int i = 0; i < NO; i++) { wr[i] = W + (size_t)(o0 + i) * K; acc[i] = 0ull; }

    const ull* aA = reinterpret_cast<const ull*>(actA);
#pragma unroll 4
    for (int k4 = 0; k4 < K4A; k4++) {
        const int kk = 4 * k4;
        ull a0 = aA[(kk + 0) * 32 + lane];
        ull a1 = aA[(kk + 1) * 32 + lane];
        ull a2 = aA[(kk + 2) * 32 + lane];
        ull a3 = aA[(kk + 3) * 32 + lane];
#pragma unroll
        for (int i = 0; i < NO; i++) {
            float4 w = *reinterpret_cast<const float4*>(wr[i] + kk);
            acc[i] = fma2(b2(w.x), a0, acc[i]);
            acc[i] = fma2(b2(w.y), a1, acc[i]);
            acc[i] = fma2(b2(w.z), a2, acc[i]);
            acc[i] = fma2(b2(w.w), a3, acc[i]);
        }
    }
    if (actB) {
        const ull* aB = reinterpret_cast<const ull*>(actB);
        const int kw0 = 4 * K4A;
#pragma unroll 4
        for (int k4 = 0; k4 < K4B; k4++) {
            const int kk = 4 * k4;
            ull a0 = aB[(kk + 0) * 32 + lane];
            ull a1 = aB[(kk + 1) * 32 + lane];
            ull a2 = aB[(kk + 2) * 32 + lane];
            ull a3 = aB[(kk + 3) * 32 + lane];
#pragma unroll
            for (int i = 0; i < NO; i++) {
                float4 w = *reinterpret_cast<const float4*>(wr[i] + kw0 + kk);
                acc[i] = fma2(b2(w.x), a0, acc[i]);
                acc[i] = fma2(b2(w.y), a1, acc[i]);
                acc[i] = fma2(b2(w.z), a2, acc[i]);
                acc[i] = fma2(b2(w.w), a3, acc[i]);
            }
        }
    }
    ull* o64 = reinterpret_cast<ull*>(out);
#pragma unroll
    for (int i = 0; i < NO; i++) {
        float bv = bias[o0 + i];
        float2 v = unpk(acc[i]);
        float vx = act_apply(v.x + bv, act);
        float vy = act_apply(v.y + bv, act);
        o64[(o0 + i) * 32 + lane] = pk(vx, vy);
    }
}

// Nout = 100 over 16 warps: warps 0-11 -> 6 outs, warps 12-15 -> 7 outs.
__device__ __forceinline__ void gemm100(
    const float* __restrict__ W, int K, const float* __restrict__ bias,
    const float* __restrict__ aA, int K4A, const float* __restrict__ aB, int K4B,
    float* __restrict__ out, int act, int warp, int lane)
{
    if (warp < 12)
        gemm_chunk<6>(W, K, bias, aA, K4A, aB, K4B, out, warp * 6, act, lane);
    else
        gemm_chunk<7>(W, K, bias, aA, K4A, aB, K4B, out, 72 + (warp - 12) * 7, act, lane);
}

// Wd3 + fused Bernoulli NLL: 4 outputs, accumulate NLL into register.
__device__ __forceinline__ void wd3_nll(
    const float* __restrict__ W, const float* __restrict__ bias,
    const float* __restrict__ hd2, const float* __restrict__ xs,
    int o0, int lane, float& nll)
{
    ull acc[4];
#pragma unroll
    for (int i = 0; i < 4; i++) acc[i] = 0ull;
    const ull* A = reinterpret_cast<const ull*>(hd2);
#pragma unroll 4
    for (int k4 = 0; k4 < 25; k4++) {
        const int kk = 4 * k4;
        ull a0 = A[(kk + 0) * 32 + lane];
        ull a1 = A[(kk + 1) * 32 + lane];
        ull a2 = A[(kk + 2) * 32 + lane];
        ull a3 = A[(kk + 3) * 32 + lane];
#pragma unroll
        for (int i = 0; i < 4; i++) {
            float4 w = *reinterpret_cast<const float4*>(W + (size_t)(o0 + i) * 100 + kk);
            acc[i] = fma2(b2(w.x), a0, acc[i]);
            acc[i] = fma2(b2(w.y), a1, acc[i]);
            acc[i] = fma2(b2(w.z), a2, acc[i]);
            acc[i] = fma2(b2(w.w), a3, acc[i]);
        }
    }
    const ull* Xs = reinterpret_cast<const ull*>(xs);
#pragma unroll
    for (int i = 0; i < 4; i++) {
        float bv = bias[o0 + i];
        float2 v  = unpk(acc[i]);
        float2 xv = unpk(Xs[(o0 + i) * 32 + lane]);
        float p0 = sigf(v.x + bv);
        float p1 = sigf(v.y + bv);
        nll -= xv.x * logf(p0 + 1e-10f) + (1.f - xv.x) * logf(1.f - p0 + 1e-10f);
        nll -= xv.y * logf(p1 + 1e-10f) + (1.f - xv.y) * logf(1.f - p1 + 1e-10f);
    }
}

// GRU segment (from R3): rows (j0,j0+1) of r,u into slots 0..3 and the n-gate
// into slots NS,NS+1 (NS=4 for Wih n_i, NS=6 for Whh n_h).
template <int NS>
__device__ __forceinline__ void gru_seg(
    ull* __restrict__ Acc,
    const float* __restrict__ W, int ldw, int j0, int col0,
    const float* __restrict__ act, int K4, int lane)
{
    const float* p0 = W + (size_t)(j0)       * ldw + col0;
    const float* p1 = p0 + ldw;
    const float* p2 = W + (size_t)(100 + j0) * ldw + col0;
    const float* p3 = p2 + ldw;
    const float* p4 = W + (size_t)(200 + j0) * ldw + col0;
    const float* p5 = p4 + ldw;
    const ull* A = reinterpret_cast<const ull*>(act);
#pragma unroll 5
    for (int k4 = 0; k4 < K4; k4++) {
        const int kk = 4 * k4;
        ull a0 = A[(kk + 0) * 32 + lane];
        ull a1 = A[(kk + 1) * 32 + lane];
        ull a2 = A[(kk + 2) * 32 + lane];
        ull a3 = A[(kk + 3) * 32 + lane];
        float4 w;
        w = *reinterpret_cast<const float4*>(p0 + kk);
        Acc[0] = fma2(b2(w.x), a0, Acc[0]); Acc[0] = fma2(b2(w.y), a1, Acc[0]);
        Acc[0] = fma2(b2(w.z), a2, Acc[0]); Acc[0] = fma2(b2(w.w), a3, Acc[0]);
        w = *reinterpret_cast<const float4*>(p1 + kk);
        Acc[1] = fma2(b2(w.x), a0, Acc[1]); Acc[1] = fma2(b2(w.y), a1, Acc[1]);
        Acc[1] = fma2(b2(w.z), a2, Acc[1]); Acc[1] = fma2(b2(w.w), a3, Acc[1]);
        w = *reinterpret_cast<const float4*>(p2 + kk);
        Acc[2] = fma2(b2(w.x), a0, Acc[2]); Acc[2] = fma2(b2(w.y), a1, Acc[2]);
        Acc[2] = fma2(b2(w.z), a2, Acc[2]); Acc[2] = fma2(b2(w.w), a3, Acc[2]);
        w = *reinterpret_cast<const float4*>(p3 + kk);
        Acc[3] = fma2(b2(w.x), a0, Acc[3]); Acc[3] = fma2(b2(w.y), a1, Acc[3]);
        Acc[3] = fma2(b2(w.z), a2, Acc[3]); Acc[3] = fma2(b2(w.w), a3, Acc[3]);
        w = *reinterpret_cast<const float4*>(p4 + kk);
        Acc[NS]   = fma2(b2(w.x), a0, Acc[NS]);   Acc[NS]   = fma2(b2(w.y), a1, Acc[NS]);
        Acc[NS]   = fma2(b2(w.z), a2, Acc[NS]);   Acc[NS]   = fma2(b2(w.w), a3, Acc[NS]);
        w = *reinterpret_cast<const float4*>(p5 + kk);
        Acc[NS+1] = fma2(b2(w.x), a0, Acc[NS+1]); Acc[NS+1] = fma2(b2(w.y), a1, Acc[NS+1]);
        Acc[NS+1] = fma2(b2(w.z), a2, Acc[NS+1]); Acc[NS+1] = fma2(b2(w.w), a3, Acc[NS+1]);
    }
}

// ---------------------------------------------------------------------------
__global__ void __launch_bounds__(NTHR, 1) vrnn_main(
    const float* __restrict__ x,      const float* __restrict__ eps,
    const float* __restrict__ Wpx,    const float* __restrict__ bpx,
    const float* __restrict__ Wpz,    const float* __restrict__ bpz,
    const float* __restrict__ Wp1,    const float* __restrict__ bp1,
    const float* __restrict__ Wp_mu,  const float* __restrict__ bp_mu,
    const float* __restrict__ Wp_sig, const float* __restrict__ bp_sig,
    const float* __restrict__ We1,    const float* __restrict__ be1,
    const float* __restrict__ We_mu,  const float* __restrict__ be_mu,
    const float* __restrict__ We_sig, const float* __restrict__ be_sig,
    const float* __restrict__ Wd1,    const float* __restrict__ bd1,
    const float* __restrict__ Wd2,    const float* __restrict__ bd2,
    const float* __restrict__ Wd3,    const float* __restrict__ bd3,
    const float* __restrict__ Wih,    const float* __restrict__ Whh,
    const float* __restrict__ bih,    const float* __restrict__ bhh,
    float* __restrict__ out)
{
    extern __shared__ float s[];
    // packed feat-major buffers: buf[(k*32+lane)*2 + half]
    float* xs   = s;                      // 28*64
    float* es   = xs   + X_DIM * TB;      // 16*64 (becomes z in place)
    float* emu  = es   + Z_DIM * TB;      // 16*64
    float* esg  = emu  + Z_DIM * TB;
    float* pmu  = esg  + Z_DIM * TB;
    float* psg  = pmu  + Z_DIM * TB;
    float* hA   = psg  + Z_DIM * TB;      // 100*64
    float* hB   = hA   + H_DIM * TB;      // 100*64 (he/hd1/hn scratch)
    float* px   = hB   + H_DIM * TB;
    float* pz   = px   + H_DIM * TB;
    float* B2   = pz   + H_DIM * TB;      // hp / hd2

    __shared__ int s_last;

    const int tid  = threadIdx.x;
    const int lane = tid & 31;
    const int warp = tid >> 5;
    const int b0   = blockIdx.x * TB;

    for (int i = tid; i < H_DIM * TB; i += NTHR) hA[i] = 0.f;

    float kl_acc = 0.f, nll_acc = 0.f;
    float* hc = hA;   // current h
    float* hs = hB;   // scratch: he -> hd1 -> hn

    for (int t = 0; t < T_STEPS; t++) {
        // ---- stage inputs into packed feat-major layout
        const float* xg = x   + ((size_t)t * B_TOT + b0) * X_DIM;
        const float* eg = eps + ((size_t)t * B_TOT + b0) * Z_DIM;
        for (int i = tid; i < X_DIM * TB; i += NTHR) {
            int r = i / X_DIM, k = i % X_DIM;
            xs[(k * 32 + (r & 31)) * 2 + (r >> 5)] = xg[i];
        }
        for (int i = tid; i < Z_DIM * TB; i += NTHR) {
            int r = i >> 4, k = i & 15;
            es[(k * 32 + (r & 31)) * 2 + (r >> 5)] = eg[i];
        }
        __syncthreads();

        // 1. px = relu(Wpx x + b)                  [100, K=28]
        gemm100(Wpx, 28, bpx, xs, 7, nullptr, 0, px, ACT_RELU, warp, lane);
        __syncthreads();

        // 2. he = relu(We1 [px;h]) -> hs           [100, K=200]
        gemm100(We1, 200, be1, px, 25, hc, 25, hs, ACT_RELU, warp, lane);
        // 3. hp = relu(Wp1 h) -> B2                [100, K=100]
        gemm100(Wp1, 100, bp1, hc, 25, nullptr, 0, B2, ACT_RELU, warp, lane);
        __syncthreads();

        // 4. heads: 4 warps per matrix, 4 outputs each (K=100)
        {
            const int m = warp >> 2, o0 = (warp & 3) * 4;
            if (m == 0)
                gemm_chunk<4>(We_mu,  100, be_mu,  hs, 25, nullptr, 0, emu, o0, ACT_LIN, lane);
            else if (m == 1)
                gemm_chunk<4>(We_sig, 100, be_sig, hs, 25, nullptr, 0, esg, o0, ACT_SP,  lane);
            else if (m == 2)
                gemm_chunk<4>(Wp_mu,  100, bp_mu,  B2, 25, nullptr, 0, pmu, o0, ACT_LIN, lane);
            else
                gemm_chunk<4>(Wp_sig, 100, bp_sig, B2, 25, nullptr, 0, psg, o0, ACT_SP,  lane);
        }
        __syncthreads();

        // 5. z = enc_mu + sqrt(enc_sig)*eps  (in place over es)
        for (int i = tid; i < Z_DIM * TB; i += NTHR)
            es[i] = emu[i] + sqrtf(esg[i]) * es[i];
        __syncthreads();

        // 6. pz = relu(Wpz z + b)                  [100, K=16]
        gemm100(Wpz, 16, bpz, es, 4, nullptr, 0, pz, ACT_RELU, warp, lane);
        __syncthreads();

        // 7. hd1 = relu(Wd1 [pz;h]) -> hs          [100, K=200]
        gemm100(Wd1, 200, bd1, pz, 25, hc, 25, hs, ACT_RELU, warp, lane);
        __syncthreads();

        // 8. hd2 = relu(Wd2 hd1) -> B2             [100, K=100]
        gemm100(Wd2, 100, bd2, hs, 25, nullptr, 0, B2, ACT_RELU, warp, lane);
        __syncthreads();

        // 9. Wd3 + fused NLL (warps 9-15, 4 outputs each)
        if (warp >= 9)
            wd3_nll(Wd3, bd3, B2, xs, (warp - 9) * 4, lane, nll_acc);

        // 10. GRU -> hn into hs (hd1 fully consumed at stage 8 barrier)
        for (int task = warp; task < 50; task += 16) {
            const int j0 = 2 * task;
            ull Acc[8];   // [r0,r1,u0,u1,ni0,ni1,nh0,nh1]
#pragma unroll
            for (int i = 0; i < 8; i++) Acc[i] = 0ull;
            gru_seg<4>(Acc, Wih, 200, j0, 0,   pz, 25, lane);
            gru_seg<4>(Acc, Wih, 200, j0, 100, px, 25, lane);
            gru_seg<6>(Acc, Whh, 100, j0, 0,   hc, 25, lane);
            const ull* h64 = reinterpret_cast<const ull*>(hc);
            ull* hn64 = reinterpret_cast<ull*>(hs);
#pragma unroll
            for (int jj = 0; jj < 2; jj++) {
                const int j = j0 + jj;
                const float br = bih[j] + bhh[j];
                const float bu = bih[100 + j] + bhh[100 + j];
                const float bn = bih[200 + j];
                const float bm = bhh[200 + j];
                float2 R = unpk(Acc[0 + jj]);
                float2 U = unpk(Acc[2 + jj]);
                float2 N = unpk(Acc[4 + jj]);
                float2 M = unpk(Acc[6 + jj]);
                float2 H = unpk(h64[j * 32 + lane]);
                float rr0 = sigf(R.x + br), rr1 = sigf(R.y + br);
                float uu0 = sigf(U.x + bu), uu1 = sigf(U.y + bu);
                float nn0 = tanhf(N.x + bn + rr0 * (M.x + bm));
                float nn1 = tanhf(N.y + bn + rr1 * (M.y + bm));
                hn64[j * 32 + lane] = pk((1.f - uu0) * nn0 + uu0 * H.x,
                                         (1.f - uu1) * nn1 + uu1 * H.y);
            }
        }
        __syncthreads();

        // 11. KL: 512 threads, one packed pair (2 rows) each
        {
            const ull* Emu = (const ull*)emu; const ull* Esg = (const ull*)esg;
            const ull* Pmu = (const ull*)pmu; const ull* Psg = (const ull*)psg;
            const int e = tid;               // Z_DIM*32 == 512 == NTHR
            float2 esv = unpk(Esg[e]);
            float2 emv = unpk(Emu[e]);
            float2 pmv = unpk(Pmu[e]);
            float2 psv = unpk(Psg[e]);
            {
                float ps = psv.x + 1e-10f, d = emv.x - pmv.x;
                kl_acc += 0.5f * (2.f * logf(ps) - 2.f * logf(esv.x)
                                  + (esv.x * esv.x + d * d) / (ps * ps) - 1.f);
            }
            {
                float ps = psv.y + 1e-10f, d = emv.y - pmv.y;
                kl_acc += 0.5f * (2.f * logf(ps) - 2.f * logf(esv.y)
                                  + (esv.y * esv.y + d * d) / (ps * ps) - 1.f);
            }
        }

        { float* tmp = hc; hc = hs; hs = tmp; }
        __syncthreads();   // protect xs/es/head buffers before next staging
    }

    // ---- block partial reduction (16 warps)
#pragma unroll
    for (int off = 16; off > 0; off >>= 1) {
        kl_acc  += __shfl_down_sync(0xffffffffu, kl_acc,  off);
        nll_acc += __shfl_down_sync(0xffffffffu, nll_acc, off);
    }
    if (lane == 0) { s[warp] = kl_acc; s[16 + warp] = nll_acc; }
    __syncthreads();
    if (tid == 0) {
        float k = 0.f, n = 0.f;
        for (int w = 0; w < 16; w++) { k += s[w]; n += s[16 + w]; }
        g_part[2 * blockIdx.x + 0] = k;
        g_part[2 * blockIdx.x + 1] = n;
        __threadfence();
        unsigned v = atomicAdd(&g_done, 1u);
        s_last = (v == (unsigned)(gridDim.x - 1)) ? 1 : 0;
    }
    __syncthreads();

    // ---- deterministic final reduction in the last-arriving block
    if (s_last) {
        if (tid < NBLK) {
            s[tid]       = g_part[2 * tid + 0];
            s[512 + tid] = g_part[2 * tid + 1];
        }
        __syncthreads();
        for (int st = NBLK / 2; st > 0; st >>= 1) {
            if (tid < st) { s[tid] += s[tid + st]; s[512 + tid] += s[512 + tid + st]; }
            __syncthreads();
        }
        if (tid == 0) {
            const float invB = 1.f / (float)B_TOT;
            out[0] = s[0] * invB;
            out[1] = s[512] * invB;
            g_done = 0;                  // reset for next graph replay
        }
    }
}

// ---------------------------------------------------------------------------
extern "C" void kernel_launch(void* const* d_in, const int* in_sizes, int n_in,
                              void* d_out, int out_size)
{
    (void)in_sizes; (void)n_in; (void)out_size;
    const float* x      = (const float*)d_in[0];
    const float* eps    = (const float*)d_in[1];
    const float* Wpx    = (const float*)d_in[2];
    const float* bpx    = (const float*)d_in[3];
    const float* Wpz    = (const float*)d_in[4];
    const float* bpz    = (const float*)d_in[5];
    const float* Wp1    = (const float*)d_in[6];
    const float* bp1    = (const float*)d_in[7];
    const float* Wp_mu  = (const float*)d_in[8];
    const float* bp_mu  = (const float*)d_in[9];
    const float* Wp_sig = (const float*)d_in[10];
    const float* bp_sig = (const float*)d_in[11];
    const float* We1    = (const float*)d_in[12];
    const float* be1    = (const float*)d_in[13];
    const float* We_mu  = (const float*)d_in[14];
    const float* be_mu  = (const float*)d_in[15];
    const float* We_sig = (const float*)d_in[16];
    const float* be_sig = (const float*)d_in[17];
    const float* Wd1    = (const float*)d_in[18];
    const float* bd1    = (const float*)d_in[19];
    const float* Wd2    = (const float*)d_in[20];
    const float* bd2    = (const float*)d_in[21];
    const float* Wd3    = (const float*)d_in[22];
    const float* bd3    = (const float*)d_in[23];
    const float* Wih    = (const float*)d_in[24];
    const float* Whh    = (const float*)d_in[25];
    const float* bih    = (const float*)d_in[26];
    const float* bhh    = (const float*)d_in[27];
    float* out = (float*)d_out;

    // xs + es + 4 z-buffers + 5 h-sized buffers
    const int smem_floats =
        X_DIM * TB + 5 * Z_DIM * TB + 5 * H_DIM * TB;   // 1792+5120+32000 = 38912
    const int smem_bytes = smem_floats * (int)sizeof(float);   // 155,648 B

    cudaFuncSetAttribute(vrnn_main,
                         cudaFuncAttributeMaxDynamicSharedMemorySize, smem_bytes);

    vrnn_main<<<NBLK, NTHR, smem_bytes>>>(
        x, eps, Wpx, bpx, Wpz, bpz, Wp1, bp1, Wp_mu, bp_mu, Wp_sig, bp_sig,
        We1, be1, We_mu, be_mu, We_sig, be_sig, Wd1, bd1, Wd2, bd2, Wd3, bd3,
        Wih, Whh, bih, bhh, out);
}